// round 1
// baseline (speedup 1.0000x reference)
#include <cuda_runtime.h>
#include <cstdint>

#define BB 2
#define NN 256
#define EE 512
#define HH 150
#define HP 160      // padded H
#define MT 128      // j-tile rows per CTA
#define PSTR 36     // P smem stride (conflict-free A loads)
#define WSTR 168    // W smem stride (168%32==8 -> conflict-free B loads)
#define HSTR 164    // h smem stride (conflict-free A loads for GEMM2)

// __device__ scratch (no allocs allowed)
__device__ float d_W1c[EE * HP];        // tf32-rounded, zero-padded
__device__ float d_W2p[HP * HP];        // tf32-rounded, zero-padded
__device__ float d_W3p[HP];             // zero-padded
__device__ float d_hi[BB * NN * HP];    // g@W1a + b1, padded
__device__ float d_hj[BB * NN * HP];    // g@W1b, padded

__device__ __forceinline__ float tf32r(float x) {
    uint32_t u;
    asm("cvt.rna.tf32.f32 %0, %1;" : "=r"(u) : "f"(x));
    return __uint_as_float(u);
}
__device__ __forceinline__ uint32_t fbits(float x) { return __float_as_uint(x); }

__device__ __forceinline__ void mma8(float* d, const uint32_t* a, const uint32_t* b) {
    asm volatile(
        "mma.sync.aligned.m16n8k8.row.col.f32.tf32.tf32.f32 "
        "{%0,%1,%2,%3},{%4,%5,%6,%7},{%8,%9},{%0,%1,%2,%3};\n"
        : "+f"(d[0]), "+f"(d[1]), "+f"(d[2]), "+f"(d[3])
        : "r"(a[0]), "r"(a[1]), "r"(a[2]), "r"(a[3]), "r"(b[0]), "r"(b[1]));
}

__device__ __forceinline__ void cp16(float* sdst, const float* gsrc) {
    uint32_t s = (uint32_t)__cvta_generic_to_shared(sdst);
    asm volatile("cp.async.cg.shared.global [%0], [%1], 16;\n" :: "r"(s), "l"(gsrc));
}

// ---------------------------------------------------------------------------
// prep: pad/round weights, init hi (=b1) / hj (=0) accumulators
// ---------------------------------------------------------------------------
__global__ void prep_kernel(const float* __restrict__ W1, const float* __restrict__ b1,
                            const float* __restrict__ W2, const float* __restrict__ W3) {
    const int S1 = EE * HP, S2 = HP * HP, S3 = HP, S4 = BB * NN * HP;
    const int total = S1 + S2 + S3 + S4 + S4;
    for (int idx = blockIdx.x * blockDim.x + threadIdx.x; idx < total;
         idx += gridDim.x * blockDim.x) {
        int t = idx;
        if (t < S1) {
            int k = t / HP, c = t % HP;
            d_W1c[t] = (c < HH) ? tf32r(W1[(1024 + k) * HH + c]) : 0.f;
            continue;
        }
        t -= S1;
        if (t < S2) {
            int k = t / HP, c = t % HP;
            d_W2p[t] = (k < HH && c < HH) ? tf32r(W2[k * HH + c]) : 0.f;
            continue;
        }
        t -= S2;
        if (t < S3) { d_W3p[t] = (t < HH) ? W3[t] : 0.f; continue; }
        t -= S3;
        if (t < S4) { int c = t % HP; d_hi[t] = (c < HH) ? b1[c] : 0.f; continue; }
        t -= S4;
        d_hj[t] = 0.f;
    }
}

// ---------------------------------------------------------------------------
// hi/hj precompute: g @ W1a (+b1 already in d_hi), g @ W1b. K-split x4 + atomicAdd.
// grid: (ksplit=4, rowblock=16, half=2), 256 threads.
// ---------------------------------------------------------------------------
__global__ void hihj_kernel(const float* __restrict__ g, const float* __restrict__ W1) {
    __shared__ float gs[32][33];
    __shared__ float Ws[32][HP];
    const int tid = threadIdx.x;
    const int kz = blockIdx.x, rb = blockIdx.y, half = blockIdx.z;
    const int row0 = rb * 32;
    const int k0 = kz * 128;
    const int ty = tid >> 4, tx = tid & 15;  // rows ty*2..+1, cols tx*10..+9

    float acc[2][10];
#pragma unroll
    for (int u = 0; u < 2; u++)
#pragma unroll
        for (int v = 0; v < 10; v++) acc[u][v] = 0.f;

    for (int kk = 0; kk < 4; kk++) {
        const int kbase = k0 + kk * 32;
        for (int q = tid; q < 32 * 32; q += 256) {
            int r = q >> 5, c = q & 31;
            gs[r][c] = g[(size_t)(row0 + r) * EE + kbase + c];
        }
        for (int q = tid; q < 32 * HP; q += 256) {
            int r = q / HP, c = q % HP;
            Ws[r][c] = (c < HH) ? W1[(size_t)(half * 512 + kbase + r) * HH + c] : 0.f;
        }
        __syncthreads();
#pragma unroll 4
        for (int k = 0; k < 32; k++) {
            float g0 = gs[ty * 2][k], g1 = gs[ty * 2 + 1][k];
#pragma unroll
            for (int v = 0; v < 10; v++) {
                float w = Ws[k][tx * 10 + v];
                acc[0][v] += g0 * w;
                acc[1][v] += g1 * w;
            }
        }
        __syncthreads();
    }
    float* dst = half ? d_hj : d_hi;
#pragma unroll
    for (int u = 0; u < 2; u++)
#pragma unroll
        for (int v = 0; v < 10; v++)
            atomicAdd(&dst[(size_t)(row0 + ty * 2 + u) * HP + tx * 10 + v], acc[u][v]);
}

// ---------------------------------------------------------------------------
// main fused kernel: one CTA per (b, i, j-block of 128). 256 threads, 8 warps (4M x 2N).
// ---------------------------------------------------------------------------
__global__ __launch_bounds__(256, 1) void pair_main(
    const float* __restrict__ g, const float* __restrict__ ment,
    const float* __restrict__ b2, const float* __restrict__ b3,
    float* __restrict__ out) {
    extern __shared__ float sm[];
    float* h_s = sm;                       // [MT][HSTR] = 20992 floats
    float* r2 = sm + MT * HSTR;            // union region, 20992 floats
    float* gi_s = r2;                      // 512
    float* hi_s = r2 + 512;                // 160
    float* Ps = r2 + 672;                  // [2][MT][PSTR] = 9216
    float* Wsb = r2 + 672 + 2 * MT * PSTR; // [2][32][WSTR] = 10752
    float* W2s = r2;                       // phase2: [80][WSTR] = 13440
    float* w3s = sm + MT * HSTR + 20992;   // 160
    float* b2s = w3s + HP;                 // 160
    float* prb = b2s + HP;                 // [2][MT]

    const int tid = threadIdx.x;
    const int jb = blockIdx.x, i = blockIdx.y, b = blockIdx.z;
    const int j0 = jb * MT;
    const int warp = tid >> 5, lane = tid & 31;
    const int wm = warp & 3, wn = warp >> 2;
    const int grp = lane >> 2, tig = lane & 3;
    const int r0 = wm * 32, c0 = wn * 80;

    // ---- phase 0 loads ----
    for (int q = tid; q < EE; q += 256) gi_s[q] = g[(size_t)(b * NN + i) * EE + q];
    for (int q = tid; q < HP; q += 256) {
        hi_s[q] = d_hi[(size_t)(b * NN + i) * HP + q];
        w3s[q] = d_W3p[q];
        b2s[q] = (q < HH) ? b2[q] : 0.f;
    }
    for (int q = tid; q < MT * (HP / 4); q += 256) {
        int r = q / (HP / 4), cq = q % (HP / 4);
        *(float4*)(h_s + r * HSTR + cq * 4) =
            *(const float4*)(d_hj + (size_t)(b * NN + j0 + r) * HP + cq * 4);
    }
    __syncthreads();

    // ---- GEMM1: acc += P @ W1c, P[j][e] = g_j[e]*g_i[e], K=512 in 16 chunks of 32 ----
    const int rP = tid >> 1, hf = tid & 1;
    float4 gr[4];
    float acc[2][10][4];
#pragma unroll
    for (int x = 0; x < 2; x++)
#pragma unroll
        for (int y = 0; y < 10; y++)
#pragma unroll
            for (int e = 0; e < 4; e++) acc[x][y][e] = 0.f;

    {  // prologue: chunk 0
        for (int q = tid; q < 1280; q += 256) {
            int row = q / 40, cq = q % 40;
            cp16(Wsb + row * WSTR + cq * 4, d_W1c + row * HP + cq * 4);
        }
        asm volatile("cp.async.commit_group;\n");
        const float* src = g + (size_t)(b * NN + j0 + rP) * EE + hf * 16;
#pragma unroll
        for (int q = 0; q < 4; q++) gr[q] = *(const float4*)(src + q * 4);
#pragma unroll
        for (int q = 0; q < 4; q++) {
            int kb = hf * 16 + q * 4;
            float4 v = gr[q];
            v.x = tf32r(v.x * gi_s[kb + 0]);
            v.y = tf32r(v.y * gi_s[kb + 1]);
            v.z = tf32r(v.z * gi_s[kb + 2]);
            v.w = tf32r(v.w * gi_s[kb + 3]);
            *(float4*)(Ps + rP * PSTR + kb) = v;
        }
        asm volatile("cp.async.wait_group 0;\n");
        __syncthreads();
    }

    for (int kc = 0; kc < 16; kc++) {
        const int cur = kc & 1, nxt = cur ^ 1;
        if (kc + 1 < 16) {
            for (int q = tid; q < 1280; q += 256) {
                int row = q / 40, cq = q % 40;
                cp16(Wsb + nxt * 32 * WSTR + row * WSTR + cq * 4,
                     d_W1c + ((kc + 1) * 32 + row) * HP + cq * 4);
            }
            asm volatile("cp.async.commit_group;\n");
            const float* src = g + (size_t)(b * NN + j0 + rP) * EE + (kc + 1) * 32 + hf * 16;
#pragma unroll
            for (int q = 0; q < 4; q++) gr[q] = *(const float4*)(src + q * 4);
        }
        const float* Pc = Ps + cur * MT * PSTR;
        const float* Wc = Wsb + cur * 32 * WSTR;
#pragma unroll
        for (int k8 = 0; k8 < 4; k8++) {
            const int kb = k8 * 8;
            uint32_t af[2][4];
#pragma unroll
            for (int mt = 0; mt < 2; mt++) {
                const float* base = Pc + (r0 + mt * 16 + grp) * PSTR + kb + tig;
                af[mt][0] = fbits(base[0]);
                af[mt][2] = fbits(base[4]);
                af[mt][1] = fbits(base[8 * PSTR]);
                af[mt][3] = fbits(base[8 * PSTR + 4]);
            }
            uint32_t bf[10][2];
#pragma unroll
            for (int nt = 0; nt < 10; nt++) {
                const float* wb = Wc + (kb + tig) * WSTR + c0 + nt * 8 + grp;
                bf[nt][0] = fbits(wb[0]);
                bf[nt][1] = fbits(wb[4 * WSTR]);
            }
#pragma unroll
            for (int mt = 0; mt < 2; mt++)
#pragma unroll
                for (int nt = 0; nt < 10; nt++) mma8(acc[mt][nt], af[mt], bf[nt]);
        }
        if (kc + 1 < 16) {
#pragma unroll
            for (int q = 0; q < 4; q++) {
                int kb = hf * 16 + q * 4;
                int kg = (kc + 1) * 32 + kb;
                float4 v = gr[q];
                v.x = tf32r(v.x * gi_s[kg + 0]);
                v.y = tf32r(v.y * gi_s[kg + 1]);
                v.z = tf32r(v.z * gi_s[kg + 2]);
                v.w = tf32r(v.w * gi_s[kg + 3]);
                *(float4*)(Ps + nxt * MT * PSTR + rP * PSTR + kb) = v;
            }
            asm volatile("cp.async.wait_group 0;\n");
        }
        __syncthreads();
    }

    // ---- epilogue1: h = relu(acc + hi[col] + hj[row][col]) -> h_s (tf32-rounded) ----
#pragma unroll
    for (int mt = 0; mt < 2; mt++)
#pragma unroll
        for (int nt = 0; nt < 10; nt++)
#pragma unroll
            for (int e = 0; e < 4; e++) {
                int row = r0 + mt * 16 + grp + ((e >> 1) << 3);
                int col = c0 + nt * 8 + tig * 2 + (e & 1);
                float v = acc[mt][nt][e] + hi_s[col] + h_s[row * HSTR + col];
                h_s[row * HSTR + col] = tf32r(fmaxf(v, 0.f));
            }
    __syncthreads();

    // ---- GEMM2: acc2 = h_s @ W2, K=160 in 2 chunks of 80 ----
    float acc2[2][10][4];
#pragma unroll
    for (int x = 0; x < 2; x++)
#pragma unroll
        for (int y = 0; y < 10; y++)
#pragma unroll
            for (int e = 0; e < 4; e++) acc2[x][y][e] = 0.f;

    for (int kc2 = 0; kc2 < 2; kc2++) {
        for (int q = tid; q < 80 * 40; q += 256) {
            int r = q / 40, cq = q % 40;
            *(float4*)(W2s + r * WSTR + cq * 4) =
                *(const float4*)(d_W2p + (kc2 * 80 + r) * HP + cq * 4);
        }
        __syncthreads();
#pragma unroll
        for (int k8 = 0; k8 < 10; k8++) {
            const int kb = k8 * 8;
            uint32_t af[2][4];
#pragma unroll
            for (int mt = 0; mt < 2; mt++) {
                const float* base = h_s + (r0 + mt * 16 + grp) * HSTR + kc2 * 80 + kb + tig;
                af[mt][0] = fbits(base[0]);
                af[mt][2] = fbits(base[4]);
                af[mt][1] = fbits(base[8 * HSTR]);
                af[mt][3] = fbits(base[8 * HSTR + 4]);
            }
            uint32_t bf[10][2];
#pragma unroll
            for (int nt = 0; nt < 10; nt++) {
                const float* wb = W2s + (kb + tig) * WSTR + c0 + nt * 8 + grp;
                bf[nt][0] = fbits(wb[0]);
                bf[nt][1] = fbits(wb[4 * WSTR]);
            }
#pragma unroll
            for (int mt = 0; mt < 2; mt++)
#pragma unroll
                for (int nt = 0; nt < 10; nt++) mma8(acc2[mt][nt], af[mt], bf[nt]);
        }
        __syncthreads();
    }

    // ---- epilogue2: h2 = relu(acc2 + b2); pair = h2 . W3; reduce; write output ----
    float p[2][2] = {{0.f, 0.f}, {0.f, 0.f}};
#pragma unroll
    for (int mt = 0; mt < 2; mt++)
#pragma unroll
        for (int nt = 0; nt < 10; nt++)
#pragma unroll
            for (int e = 0; e < 4; e++) {
                int col = c0 + nt * 8 + tig * 2 + (e & 1);
                float h2 = fmaxf(acc2[mt][nt][e] + b2s[col], 0.f);
                p[mt][e >> 1] += h2 * w3s[col];
            }
#pragma unroll
    for (int mt = 0; mt < 2; mt++)
#pragma unroll
        for (int hh = 0; hh < 2; hh++) {
            float v = p[mt][hh];
            v += __shfl_xor_sync(0xffffffffu, v, 1);
            v += __shfl_xor_sync(0xffffffffu, v, 2);
            p[mt][hh] = v;
        }
    if (tig == 0) {
#pragma unroll
        for (int mt = 0; mt < 2; mt++)
#pragma unroll
            for (int hh = 0; hh < 2; hh++) {
                int row = r0 + mt * 16 + grp + hh * 8;
                prb[wn * MT + row] = p[mt][hh];
            }
    }
    __syncthreads();
    if (tid < MT) {
        int j = j0 + tid;
        float pair = prb[tid] + prb[MT + tid] + b3[0];
        float mi = ment[b * NN + i];
        float mj = ment[b * NN + j];
        out[((size_t)(b * NN + i)) * NN + j] = (mi + mj + pair) * (1.f / 3.f);
    }
}

// ---------------------------------------------------------------------------
extern "C" void kernel_launch(void* const* d_in, const int* in_sizes, int n_in,
                              void* d_out, int out_size) {
    const float* g  = (const float*)d_in[0];
    const float* m  = (const float*)d_in[1];
    const float* W1 = (const float*)d_in[2];
    const float* b1 = (const float*)d_in[3];
    const float* W2 = (const float*)d_in[4];
    const float* b2 = (const float*)d_in[5];
    const float* W3 = (const float*)d_in[6];
    const float* b3 = (const float*)d_in[7];
    float* out = (float*)d_out;
    (void)in_sizes; (void)n_in; (void)out_size;

    prep_kernel<<<544, 256>>>(W1, b1, W2, W3);
    hihj_kernel<<<dim3(4, 16, 2), 256>>>(g, W1);

    const int smem_bytes = (MT * HSTR + 20992 + HP + HP + 2 * MT) * 4;  // 170240 B
    cudaFuncSetAttribute(pair_main, cudaFuncAttributeMaxDynamicSharedMemorySize, smem_bytes);
    pair_main<<<dim3(NN / MT, NN, BB), 256, smem_bytes>>>(g, m, b2, b3, out);
}

// round 3
// speedup vs baseline: 2.0062x; 2.0062x over previous
#include <cuda_runtime.h>
#include <cuda_fp16.h>
#include <cstdint>

#define BB 2
#define NN 256
#define EE 512
#define HH 150
#define HP 160

// smem byte offsets
#define SM_A   0        // A chunks: 2 x [128 rows x 80B] = 20480
#define SM_B   20480    // B chunks: 2 x [160 rows x 80B] = 25600
#define SM_H   46080    // h: [128 rows x 336B] = 43008
#define SM_HI  89088    // hi fp32 [160]
#define SM_B2  89728    // b2 fp32 [160]
#define SM_W3  90368    // W3 fp32 [160]
#define SM_PRB 91008    // 4 x 128 fp32
#define SMEM_BYTES 93056

// device scratch
__device__ __half d_gh[BB * NN * EE];     // fp16 g
__device__ __half d_W1cTh[HP * EE];       // W1c^T [n][k] fp16, zero-padded
__device__ __half d_W2Th[HP * HP];        // W2^T  [n][k] fp16, zero-padded
__device__ float  d_hi[BB * NN * HP];     // g@W1a + b1 (fp32)
__device__ float  d_hj[BB * NN * HP];     // g@W1b (fp32 accum)
__device__ __half d_hjh[BB * NN * HP];    // fp16 copy of d_hj

// ---- helpers ----
__device__ __forceinline__ uint32_t h2mul(uint32_t a, uint32_t b) {
    uint32_t r;
    asm("mul.rn.f16x2 %0, %1, %2;" : "=r"(r) : "r"(a), "r"(b));
    return r;
}
__device__ __forceinline__ float2 h2f2(uint32_t h) {
    __half2 v = *reinterpret_cast<__half2*>(&h);
    return __half22float2(v);
}
__device__ __forceinline__ uint32_t f2h2(float lo, float hi) {
    uint32_t r;
    asm("cvt.rn.f16x2.f32 %0, %1, %2;" : "=r"(r) : "f"(hi), "f"(lo));
    return r;
}
__device__ __forceinline__ void cp16s(uint32_t dst, const void* src) {
    asm volatile("cp.async.cg.shared.global [%0], [%1], 16;" :: "r"(dst), "l"(src));
}
__device__ __forceinline__ void sts128(uint32_t a, uint4 v) {
    asm volatile("st.shared.v4.b32 [%0], {%1,%2,%3,%4};"
                 :: "r"(a), "r"(v.x), "r"(v.y), "r"(v.z), "r"(v.w));
}
__device__ __forceinline__ void sts32(uint32_t a, uint32_t v) {
    asm volatile("st.shared.b32 [%0], %1;" :: "r"(a), "r"(v));
}

#define LDSM4(r0, r1, r2, r3, a)                                              \
    asm volatile("ldmatrix.sync.aligned.m8n8.x4.shared.b16 {%0,%1,%2,%3}, [%4];" \
                 : "=r"(r0), "=r"(r1), "=r"(r2), "=r"(r3) : "r"(a))
#define LDSM2(r0, r1, a)                                                      \
    asm volatile("ldmatrix.sync.aligned.m8n8.x2.shared.b16 {%0,%1}, [%2];"    \
                 : "=r"(r0), "=r"(r1) : "r"(a))

__device__ __forceinline__ void mma16(float* d, const uint32_t* a, const uint32_t* b) {
    asm volatile(
        "mma.sync.aligned.m16n8k16.row.col.f32.f16.f16.f32 "
        "{%0,%1,%2,%3},{%4,%5,%6,%7},{%8,%9},{%0,%1,%2,%3};"
        : "+f"(d[0]), "+f"(d[1]), "+f"(d[2]), "+f"(d[3])
        : "r"(a[0]), "r"(a[1]), "r"(a[2]), "r"(a[3]), "r"(b[0]), "r"(b[1]));
}

// ---------------------------------------------------------------------------
// prep: fp16 conversions/transposes/padding + hi/hj accumulator init
// ---------------------------------------------------------------------------
__global__ void prep_kernel(const float* __restrict__ g, const float* __restrict__ W1,
                            const float* __restrict__ W2, const float* __restrict__ b1) {
    const int S0 = BB * NN * EE, S1 = HP * EE, S2 = HP * HP, S4 = BB * NN * HP;
    const int total = S0 + S1 + S2 + S4 + S4;
    for (int idx = blockIdx.x * blockDim.x + threadIdx.x; idx < total;
         idx += gridDim.x * blockDim.x) {
        int t = idx;
        if (t < S0) { d_gh[t] = __float2half(g[t]); continue; }
        t -= S0;
        if (t < S1) {
            int n = t >> 9, k = t & 511;
            d_W1cTh[t] = (n < HH) ? __float2half(W1[(size_t)(2 * EE + k) * HH + n])
                                  : __float2half(0.f);
            continue;
        }
        t -= S1;
        if (t < S2) {
            int n = t / HP, k = t % HP;
            d_W2Th[t] = (n < HH && k < HH) ? __float2half(W2[(size_t)k * HH + n])
                                           : __float2half(0.f);
            continue;
        }
        t -= S2;
        if (t < S4) { int c = t % HP; d_hi[t] = (c < HH) ? b1[c] : 0.f; continue; }
        t -= S4;
        d_hj[t] = 0.f;
    }
}

// ---------------------------------------------------------------------------
// hi/hj precompute: g@W1a (+b1 already in d_hi), g@W1b. K-split x4 + atomicAdd.
// ---------------------------------------------------------------------------
__global__ void hihj_kernel(const float* __restrict__ g, const float* __restrict__ W1) {
    __shared__ float gs[32][33];
    __shared__ float Ws[32][HP];
    const int tid = threadIdx.x;
    const int kz = blockIdx.x, rb = blockIdx.y, half = blockIdx.z;
    const int row0 = rb * 32;
    const int k0 = kz * 128;
    const int ty = tid >> 4, tx = tid & 15;

    float acc[2][10];
#pragma unroll
    for (int u = 0; u < 2; u++)
#pragma unroll
        for (int v = 0; v < 10; v++) acc[u][v] = 0.f;

    for (int kk = 0; kk < 4; kk++) {
        const int kbase = k0 + kk * 32;
        for (int q = tid; q < 32 * 32; q += 256) {
            int r = q >> 5, c = q & 31;
            gs[r][c] = g[(size_t)(row0 + r) * EE + kbase + c];
        }
        for (int q = tid; q < 32 * HP; q += 256) {
            int r = q / HP, c = q % HP;
            Ws[r][c] = (c < HH) ? W1[(size_t)(half * 512 + kbase + r) * HH + c] : 0.f;
        }
        __syncthreads();
#pragma unroll 4
        for (int k = 0; k < 32; k++) {
            float g0 = gs[ty * 2][k], g1 = gs[ty * 2 + 1][k];
#pragma unroll
            for (int v = 0; v < 10; v++) {
                float w = Ws[k][tx * 10 + v];
                acc[0][v] += g0 * w;
                acc[1][v] += g1 * w;
            }
        }
        __syncthreads();
    }
    float* dst = half ? d_hj : d_hi;
#pragma unroll
    for (int u = 0; u < 2; u++)
#pragma unroll
        for (int v = 0; v < 10; v++)
            atomicAdd(&dst[(size_t)(row0 + ty * 2 + u) * HP + tx * 10 + v], acc[u][v]);
}

__global__ void cvt_hj_kernel() {
    int t = blockIdx.x * 256 + threadIdx.x;
    if (t < BB * NN * HP) d_hjh[t] = __float2half(d_hj[t]);
}

// ---------------------------------------------------------------------------
// main fused fp16 mma kernel: CTA = (jb, i, b). M=128 j-rows, N=160, K1=512, K2=160.
// 8 warps as 2(M) x 4(N): warp tile 64 x 40.
// ---------------------------------------------------------------------------
__global__ __launch_bounds__(256, 1) void pair_fp16(
    const float* __restrict__ ment, const float* __restrict__ b2,
    const float* __restrict__ W3, const float* __restrict__ b3,
    float* __restrict__ out) {
    extern __shared__ __align__(16) unsigned char smem[];
    const uint32_t sb = (uint32_t)__cvta_generic_to_shared(smem);
    float* hi_s = (float*)(smem + SM_HI);
    float* b2_s = (float*)(smem + SM_B2);
    float* w3_s = (float*)(smem + SM_W3);
    float* prb  = (float*)(smem + SM_PRB);

    const int tid = threadIdx.x, wid = tid >> 5, lane = tid & 31;
    const int jb = blockIdx.x, i = blockIdx.y, b = blockIdx.z;
    const int j0 = jb * 128;
    const int wm = wid >> 2, wn = wid & 3, grp = lane >> 2, tig = lane & 3;

    for (int q = tid; q < HP; q += 256) {
        hi_s[q] = d_hi[(size_t)(b * NN + i) * HP + q];
        b2_s[q] = (q < HH) ? b2[q] : 0.f;
        w3_s[q] = (q < HH) ? W3[q] : 0.f;
    }

    const __half* gj = d_gh + (size_t)(b * NN + j0) * EE;
    const __half* gi = d_gh + (size_t)(b * NN + i) * EE;

    // lane-invariant ldmatrix address offsets (conflict-free: stride 80B / 336B)
    const uint32_t aoff  = (uint32_t)((wm * 64 + (lane & 7) + ((lane >> 3) & 1) * 8) * 80 +
                                      (lane >> 4) * 16);
    const uint32_t aoffH = (uint32_t)((wm * 64 + (lane & 7) + ((lane >> 3) & 1) * 8) * 336 +
                                      (lane >> 4) * 16);
    const uint32_t boff4 = (uint32_t)((wn * 40 + (lane & 7) + ((lane >> 4) & 1) * 8) * 80 +
                                      ((lane >> 3) & 1) * 16);
    const uint32_t boff2 = (uint32_t)((wn * 40 + 32 + (lane & 7)) * 80 +
                                      ((lane >> 3) & 1) * 16);

    // ---- stage chunk 0: A via cp.async, B = fp16(gi) * fp16(W1cT) ----
#pragma unroll
    for (int t = 0; t < 2; t++) {
        int p = tid + t * 256;
        int row = p >> 2, u = p & 3;
        cp16s(sb + SM_A + row * 80 + u * 16, gj + (size_t)row * EE + u * 8);
    }
    asm volatile("cp.async.commit_group;");
    {
        uint4 wreg[3], greg[3];
#pragma unroll
        for (int t = 0; t < 3; t++) {
            int q = tid + t * 256;
            if (q < 640) {
                int n = q >> 2, u = q & 3;
                wreg[t] = *(const uint4*)(d_W1cTh + (size_t)n * EE + u * 8);
                greg[t] = *(const uint4*)(gi + u * 8);
            }
        }
#pragma unroll
        for (int t = 0; t < 3; t++) {
            int q = tid + t * 256;
            if (q < 640) {
                int n = q >> 2, u = q & 3;
                uint4 o;
                o.x = h2mul(wreg[t].x, greg[t].x);
                o.y = h2mul(wreg[t].y, greg[t].y);
                o.z = h2mul(wreg[t].z, greg[t].z);
                o.w = h2mul(wreg[t].w, greg[t].w);
                sts128(sb + SM_B + n * 80 + u * 16, o);
            }
        }
    }
    asm volatile("cp.async.wait_group 0;");
    __syncthreads();

    // ---- GEMM1: K=512 in 16 chunks of 32, double-buffered ----
    float acc[4][5][4];
#pragma unroll
    for (int x = 0; x < 4; x++)
#pragma unroll
        for (int y = 0; y < 5; y++)
#pragma unroll
            for (int e = 0; e < 4; e++) acc[x][y][e] = 0.f;

    for (int kc = 0; kc < 16; kc++) {
        const int cur = kc & 1, nxt = cur ^ 1;
        uint4 wreg[3], greg[3];
        if (kc < 15) {
            const int kn = kc + 1;
#pragma unroll
            for (int t = 0; t < 2; t++) {
                int p = tid + t * 256;
                int row = p >> 2, u = p & 3;
                cp16s(sb + SM_A + nxt * 10240 + row * 80 + u * 16,
                      gj + (size_t)row * EE + kn * 32 + u * 8);
            }
            asm volatile("cp.async.commit_group;");
#pragma unroll
            for (int t = 0; t < 3; t++) {
                int q = tid + t * 256;
                if (q < 640) {
                    int n = q >> 2, u = q & 3;
                    wreg[t] = *(const uint4*)(d_W1cTh + (size_t)n * EE + kn * 32 + u * 8);
                    greg[t] = *(const uint4*)(gi + kn * 32 + u * 8);
                }
            }
        }
        const uint32_t ab0 = sb + SM_A + cur * 10240;
        const uint32_t bb0 = sb + SM_B + cur * 12800;
#pragma unroll
        for (int ks = 0; ks < 2; ks++) {
            uint32_t a[4][4], bf[5][2];
            const uint32_t abase = ab0 + aoff + ks * 32;
            LDSM4(a[0][0], a[0][1], a[0][2], a[0][3], abase);
            LDSM4(a[1][0], a[1][1], a[1][2], a[1][3], abase + 1280);
            LDSM4(a[2][0], a[2][1], a[2][2], a[2][3], abase + 2560);
            LDSM4(a[3][0], a[3][1], a[3][2], a[3][3], abase + 3840);
            const uint32_t bbase = bb0 + ks * 32;
            LDSM4(bf[0][0], bf[0][1], bf[1][0], bf[1][1], bbase + boff4);
            LDSM4(bf[2][0], bf[2][1], bf[3][0], bf[3][1], bbase + boff4 + 1280);
            LDSM2(bf[4][0], bf[4][1], bbase + boff2);
#pragma unroll
            for (int mt = 0; mt < 4; mt++)
#pragma unroll
                for (int nt = 0; nt < 5; nt++) mma16(acc[mt][nt], a[mt], bf[nt]);
        }
        if (kc < 15) {
#pragma unroll
            for (int t = 0; t < 3; t++) {
                int q = tid + t * 256;
                if (q < 640) {
                    int n = q >> 2, u = q & 3;
                    uint4 o;
                    o.x = h2mul(wreg[t].x, greg[t].x);
                    o.y = h2mul(wreg[t].y, greg[t].y);
                    o.z = h2mul(wreg[t].z, greg[t].z);
                    o.w = h2mul(wreg[t].w, greg[t].w);
                    sts128(sb + SM_B + nxt * 12800 + n * 80 + u * 16, o);
                }
            }
            asm volatile("cp.async.wait_group 0;");
        }
        __syncthreads();
    }

    // ---- prefetch W2 chunk 0 while doing epilogue1 ----
#pragma unroll
    for (int t = 0; t < 3; t++) {
        int q = tid + t * 256;
        if (q < 640) {
            int n = q >> 2, u = q & 3;
            cp16s(sb + SM_B + n * 80 + u * 16, d_W2Th + (size_t)n * HP + u * 8);
        }
    }
    asm volatile("cp.async.commit_group;");

    // ---- epilogue1: h = relu(acc + hi + hj) -> fp16 in SM_H ----
#pragma unroll
    for (int mt = 0; mt < 4; mt++) {
#pragma unroll
        for (int hrow = 0; hrow < 2; hrow++) {
            const int r = wm * 64 + mt * 16 + grp + hrow * 8;
            const __half* hjrow = d_hjh + (size_t)(b * NN + j0 + r) * HP;
#pragma unroll
            for (int nt = 0; nt < 5; nt++) {
                const int col = wn * 40 + nt * 8 + 2 * tig;
                uint32_t hjp = *(const uint32_t*)(hjrow + col);
                float2 hjf = h2f2(hjp);
                float x0 = fmaxf(acc[mt][nt][hrow * 2 + 0] + hi_s[col] + hjf.x, 0.f);
                float x1 = fmaxf(acc[mt][nt][hrow * 2 + 1] + hi_s[col + 1] + hjf.y, 0.f);
                sts32(sb + SM_H + r * 336 + col * 2, f2h2(x0, x1));
            }
        }
    }
    asm volatile("cp.async.wait_group 0;");
    __syncthreads();

    // ---- GEMM2: K=160 in 5 chunks of 32, A = h (stride 336), B = W2T chunks ----
    float acc2[4][5][4];
#pragma unroll
    for (int x = 0; x < 4; x++)
#pragma unroll
        for (int y = 0; y < 5; y++)
#pragma unroll
            for (int e = 0; e < 4; e++) acc2[x][y][e] = 0.f;

    for (int c = 0; c < 5; c++) {
        const int cur = c & 1, nxt = cur ^ 1;
        if (c < 4) {
#pragma unroll
            for (int t = 0; t < 3; t++) {
                int q = tid + t * 256;
                if (q < 640) {
                    int n = q >> 2, u = q & 3;
                    cp16s(sb + SM_B + nxt * 12800 + n * 80 + u * 16,
                          d_W2Th + (size_t)n * HP + (c + 1) * 32 + u * 8);
                }
            }
            asm volatile("cp.async.commit_group;");
        }
        const uint32_t bb0 = sb + SM_B + cur * 12800;
#pragma unroll
        for (int ks = 0; ks < 2; ks++) {
            uint32_t a[4][4], bf[5][2];
            const uint32_t abase = sb + SM_H + aoffH + c * 64 + ks * 32;
            LDSM4(a[0][0], a[0][1], a[0][2], a[0][3], abase);
            LDSM4(a[1][0], a[1][1], a[1][2], a[1][3], abase + 5376);
            LDSM4(a[2][0], a[2][1], a[2][2], a[2][3], abase + 10752);
            LDSM4(a[3][0], a[3][1], a[3][2], a[3][3], abase + 16128);
            const uint32_t bbase = bb0 + ks * 32;
            LDSM4(bf[0][0], bf[0][1], bf[1][0], bf[1][1], bbase + boff4);
            LDSM4(bf[2][0], bf[2][1], bf[3][0], bf[3][1], bbase + boff4 + 1280);
            LDSM2(bf[4][0], bf[4][1], bbase + boff2);
#pragma unroll
            for (int mt = 0; mt < 4; mt++)
#pragma unroll
                for (int nt = 0; nt < 5; nt++) mma16(acc2[mt][nt], a[mt], bf[nt]);
        }
        if (c < 4) asm volatile("cp.async.wait_group 0;");
        __syncthreads();
    }

    // ---- epilogue2: pair = relu(acc2 + b2) . W3; reduce; write out ----
#pragma unroll
    for (int mt = 0; mt < 4; mt++) {
        float s0 = 0.f, s1 = 0.f;
#pragma unroll
        for (int nt = 0; nt < 5; nt++) {
            const int col = wn * 40 + nt * 8 + 2 * tig;
            s0 += fmaxf(acc2[mt][nt][0] + b2_s[col], 0.f) * w3_s[col];
            s0 += fmaxf(acc2[mt][nt][1] + b2_s[col + 1], 0.f) * w3_s[col + 1];
            s1 += fmaxf(acc2[mt][nt][2] + b2_s[col], 0.f) * w3_s[col];
            s1 += fmaxf(acc2[mt][nt][3] + b2_s[col + 1], 0.f) * w3_s[col + 1];
        }
        s0 += __shfl_xor_sync(0xffffffffu, s0, 1);
        s0 += __shfl_xor_sync(0xffffffffu, s0, 2);
        s1 += __shfl_xor_sync(0xffffffffu, s1, 1);
        s1 += __shfl_xor_sync(0xffffffffu, s1, 2);
        if (tig == 0) {
            prb[wn * 128 + wm * 64 + mt * 16 + grp] = s0;
            prb[wn * 128 + wm * 64 + mt * 16 + grp + 8] = s1;
        }
    }
    __syncthreads();

    if (tid < 128) {
        const int j = j0 + tid;
        float pair = prb[tid] + prb[128 + tid] + prb[256 + tid] + prb[384 + tid] + b3[0];
        float mi = ment[b * NN + i];
        float mj = ment[b * NN + j];
        out[(size_t)(b * NN + i) * NN + j] = (mi + mj + pair) * (1.f / 3.f);
    }
}

// ---------------------------------------------------------------------------
extern "C" void kernel_launch(void* const* d_in, const int* in_sizes, int n_in,
                              void* d_out, int out_size) {
    const float* g  = (const float*)d_in[0];
    const float* m  = (const float*)d_in[1];
    const float* W1 = (const float*)d_in[2];
    const float* b1 = (const float*)d_in[3];
    const float* W2 = (const float*)d_in[4];
    const float* b2 = (const float*)d_in[5];
    const float* W3 = (const float*)d_in[6];
    const float* b3 = (const float*)d_in[7];
    float* out = (float*)d_out;
    (void)in_sizes; (void)n_in; (void)out_size;

    prep_kernel<<<544, 256>>>(g, W1, W2, b1);
    hihj_kernel<<<dim3(4, 16, 2), 256>>>(g, W1);
    cvt_hj_kernel<<<320, 256>>>();

    cudaFuncSetAttribute(pair_fp16, cudaFuncAttributeMaxDynamicSharedMemorySize, SMEM_BYTES);
    pair_fp16<<<dim3(NN / 128, NN, BB), 256, SMEM_BYTES>>>(m, b2, W3, b3, out);
}